// round 1
// baseline (speedup 1.0000x reference)
#include <cuda_runtime.h>

#define E_TOTAL   20000
#define FDIM      17
#define TILE_E    40
#define CO_TILE   8
#define W3S_ROWS  768          // CO_TILE*32*3
#define W3S_PITCH 33           // padded row (stride 33 -> conflict-free)
#define SMEM_FLOATS (W3S_ROWS*W3S_PITCH + TILE_E*32 + TILE_E*27)
#define SMEM_BYTES  (SMEM_FLOATS * 4)

// scratch for h2 (radial MLP output), allocation-free per harness rules
__device__ float g_h[E_TOTAL * 32];

// ---------------------------------------------------------------------------
// Kernel 1: radial MLP  f[E,17] -> h2[E,32]
// One warp per edge; lane j owns output channel j.
// ---------------------------------------------------------------------------
__global__ __launch_bounds__(256) void mlp_kernel(
    const float* __restrict__ f,
    const float* __restrict__ w1, const float* __restrict__ b1,
    const float* __restrict__ g1, const float* __restrict__ be1,
    const float* __restrict__ w2, const float* __restrict__ b2,
    const float* __restrict__ g2, const float* __restrict__ be2)
{
    __shared__ float w1s[32 * FDIM];
    __shared__ float w2s[32 * 33];     // padded rows -> conflict-free
    __shared__ float b1s[32], g1s[32], be1s[32];
    __shared__ float b2s[32], g2s[32], be2s[32];

    int tid = threadIdx.x;
    for (int i = tid; i < 32 * FDIM; i += 256) w1s[i] = w1[i];
    for (int i = tid; i < 32 * 32;  i += 256) w2s[(i >> 5) * 33 + (i & 31)] = w2[i];
    if (tid < 32) {
        b1s[tid] = b1[tid]; g1s[tid] = g1[tid]; be1s[tid] = be1[tid];
        b2s[tid] = b2[tid]; g2s[tid] = g2[tid]; be2s[tid] = be2[tid];
    }
    __syncthreads();

    int warp = tid >> 5, lane = tid & 31;
    int e = blockIdx.x * 8 + warp;
    if (e >= E_TOTAL) return;

    // layer 1: each lane needs all 17 f values -> broadcast via shfl
    float fv = (lane < FDIM) ? f[e * FDIM + lane] : 0.0f;
    float h = b1s[lane];
    #pragma unroll
    for (int k = 0; k < FDIM; k++) {
        float fk = __shfl_sync(0xffffffffu, fv, k);
        h = fmaf(fk, w1s[lane * FDIM + k], h);
    }
    // LN1 + ReLU
    float s = h;
    #pragma unroll
    for (int o = 16; o > 0; o >>= 1) s += __shfl_xor_sync(0xffffffffu, s, o);
    float mu = s * (1.0f / 32.0f);
    float d = h - mu;
    float v = d * d;
    #pragma unroll
    for (int o = 16; o > 0; o >>= 1) v += __shfl_xor_sync(0xffffffffu, v, o);
    float x = d * rsqrtf(v * (1.0f / 32.0f) + 1e-5f) * g1s[lane] + be1s[lane];
    x = fmaxf(x, 0.0f);

    // layer 2
    float h2 = b2s[lane];
    #pragma unroll
    for (int k = 0; k < 32; k++) {
        float xk = __shfl_sync(0xffffffffu, x, k);
        h2 = fmaf(xk, w2s[lane * 33 + k], h2);
    }
    // LN2 + ReLU
    s = h2;
    #pragma unroll
    for (int o = 16; o > 0; o >>= 1) s += __shfl_xor_sync(0xffffffffu, s, o);
    mu = s * (1.0f / 32.0f);
    d = h2 - mu;
    v = d * d;
    #pragma unroll
    for (int o = 16; o > 0; o >>= 1) v += __shfl_xor_sync(0xffffffffu, v, o);
    float x2 = d * rsqrtf(v * (1.0f / 32.0f) + 1e-5f) * g2s[lane] + be2s[lane];
    x2 = fmaxf(x2, 0.0f);

    g_h[e * 32 + lane] = x2;
}

// ---------------------------------------------------------------------------
// Kernel 2: r = h2 @ w3.T + b3 fused with the frequency contraction.
// grid = (E/TILE_E, 32/CO_TILE). 256 threads; thread = (co_rel, ci) pair.
// w3 slice staged in padded smem, then cached in 96 registers per thread
// and reused across TILE_E edges.
// ---------------------------------------------------------------------------
__global__ __launch_bounds__(256, 2) void conv_kernel(
    const float* __restrict__ basis,
    const float* __restrict__ w3,
    const float* __restrict__ b3,
    float* __restrict__ out)
{
    extern __shared__ float smem[];
    float* w3s = smem;                           // 768 * 33
    float* h_s = smem + W3S_ROWS * W3S_PITCH;    // TILE_E * 32
    float* B_s = h_s + TILE_E * 32;              // TILE_E * 27

    int tid = threadIdx.x;
    int e0  = blockIdx.x * TILE_E;
    int cy  = blockIdx.y;                        // co tile index (0..3)

    // stage w3 slice (coalesced gmem, conflict-free smem stores)
    const float* w3g = w3 + (size_t)cy * (W3S_ROWS * 32);
    for (int i = tid; i < W3S_ROWS * 32; i += 256)
        w3s[(i >> 5) * W3S_PITCH + (i & 31)] = w3g[i];
    // stage h tile
    for (int i = tid; i < TILE_E * 32; i += 256)
        h_s[i] = g_h[(size_t)e0 * 32 + i];
    // stage basis tile [e][do][di][fq]
    for (int i = tid; i < TILE_E * 27; i += 256)
        B_s[i] = basis[(size_t)e0 * 27 + i];
    __syncthreads();

    int co_r = tid >> 5, ci = tid & 31;
    int co = cy * CO_TILE + co_r;

    // register-cache this thread's 3 w3 rows (96 floats); stride 99 == 3 mod 32
    float w3r[96];
    #pragma unroll
    for (int ff = 0; ff < 3; ff++)
        #pragma unroll
        for (int k = 0; k < 32; k++)
            w3r[ff * 32 + k] = w3s[(tid * 3 + ff) * W3S_PITCH + k];

    size_t jb = ((size_t)co * 32 + ci) * 3;
    float b30 = b3[jb], b31 = b3[jb + 1], b32 = b3[jb + 2];

    float* outb = out + (size_t)e0 * 9216 + (size_t)(co * 3) * 96 + ci * 3;

    for (int e = 0; e < TILE_E; e++) {
        const float* hp = h_s + e * 32;
        float R0 = b30, R1 = b31, R2 = b32;
        #pragma unroll
        for (int k4 = 0; k4 < 8; k4++) {
            float4 hv = *reinterpret_cast<const float4*>(hp + k4 * 4);
            R0 = fmaf(hv.x, w3r[0 * 32 + k4 * 4 + 0], R0);
            R1 = fmaf(hv.x, w3r[1 * 32 + k4 * 4 + 0], R1);
            R2 = fmaf(hv.x, w3r[2 * 32 + k4 * 4 + 0], R2);
            R0 = fmaf(hv.y, w3r[0 * 32 + k4 * 4 + 1], R0);
            R1 = fmaf(hv.y, w3r[1 * 32 + k4 * 4 + 1], R1);
            R2 = fmaf(hv.y, w3r[2 * 32 + k4 * 4 + 1], R2);
            R0 = fmaf(hv.z, w3r[0 * 32 + k4 * 4 + 2], R0);
            R1 = fmaf(hv.z, w3r[1 * 32 + k4 * 4 + 2], R1);
            R2 = fmaf(hv.z, w3r[2 * 32 + k4 * 4 + 2], R2);
            R0 = fmaf(hv.w, w3r[0 * 32 + k4 * 4 + 3], R0);
            R1 = fmaf(hv.w, w3r[1 * 32 + k4 * 4 + 3], R1);
            R2 = fmaf(hv.w, w3r[2 * 32 + k4 * 4 + 3], R2);
        }
        const float* Bp = B_s + e * 27;
        float* op = outb + (size_t)e * 9216;
        #pragma unroll
        for (int dd = 0; dd < 3; dd++)
            #pragma unroll
            for (int di = 0; di < 3; di++) {
                float vv = fmaf(R2, Bp[dd * 9 + di * 3 + 2],
                           fmaf(R1, Bp[dd * 9 + di * 3 + 1],
                                R0 * Bp[dd * 9 + di * 3 + 0]));
                op[dd * 96 + di] = vv;
            }
    }
}

// ---------------------------------------------------------------------------
extern "C" void kernel_launch(void* const* d_in, const int* in_sizes, int n_in,
                              void* d_out, int out_size)
{
    const float* f     = (const float*)d_in[0];
    const float* basis = (const float*)d_in[1];
    const float* w1    = (const float*)d_in[2];
    const float* b1    = (const float*)d_in[3];
    const float* g1    = (const float*)d_in[4];
    const float* be1   = (const float*)d_in[5];
    const float* w2    = (const float*)d_in[6];
    const float* b2    = (const float*)d_in[7];
    const float* g2    = (const float*)d_in[8];
    const float* be2   = (const float*)d_in[9];
    const float* w3    = (const float*)d_in[10];
    const float* b3    = (const float*)d_in[11];
    float* out = (float*)d_out;

    mlp_kernel<<<(E_TOTAL + 7) / 8, 256>>>(f, w1, b1, g1, be1, w2, b2, g2, be2);

    cudaFuncSetAttribute(conv_kernel,
                         cudaFuncAttributeMaxDynamicSharedMemorySize, SMEM_BYTES);
    dim3 grid(E_TOTAL / TILE_E, 32 / CO_TILE);
    conv_kernel<<<grid, 256, SMEM_BYTES>>>(basis, w3, b3, out);
}